// round 12
// baseline (speedup 1.0000x reference)
#include <cuda_runtime.h>
#include <math.h>
typedef unsigned long long ull;

#define TSTEPS 512
#define HDIM 1024

#define FFMA2(acc,a,b) asm("fma.rn.f32x2 %0, %1, %2, %0;" : "+l"(acc) : "l"(a), "l"(b))
__device__ __forceinline__ float psum(ull v){
    float x, y;
    asm("mov.b64 {%0,%1}, %2;" : "=f"(x), "=f"(y) : "l"(v));
    return x + y;
}

__device__ int g_cnt[4 * TSTEPS];
__global__ void reset_kernel(){
    int i = blockIdx.x * blockDim.x + threadIdx.x;
    if (i < 4 * TSTEPS) g_cnt[i] = 0;
}

// ---------------------------------------------------------------------------
// Phase 1 (unchanged, proven ~2.3ms): C = A @ W + b, 128x128, FFMA2 K-paired.
// ---------------------------------------------------------------------------
#define SA 20
__global__ void __launch_bounds__(256, 1) gemm_xw(
    const float* __restrict__ A, const float* __restrict__ W,
    const float* __restrict__ bias, float* __restrict__ C)
{
    __shared__ float sA[2][128 * SA];
    __shared__ float sB[2][8 * 256];
    const int tid = threadIdx.x;
    const int n0 = blockIdx.x * 128, m0 = blockIdx.y * 128;
    const int ty = tid >> 4, tx = tid & 15;
    const int ar = tid >> 1, ah = (tid & 1) * 8;
    const int wn = tid & 127, wk0 = tid >> 7;

    ull acc[8][8];
    #pragma unroll
    for (int i = 0; i < 8; i++)
        #pragma unroll
        for (int j = 0; j < 8; j++) acc[i][j] = 0ull;

    const float* Ap = A + (size_t)(m0 + ar) * HDIM + ah;
    float4 pa0, pa1; float pw[8];
    pa0 = *(const float4*)Ap;
    pa1 = *(const float4*)(Ap + 4);
    #pragma unroll
    for (int q = 0; q < 4; q++) {
        int kp = wk0 + q * 2;
        pw[q*2+0] = W[(size_t)(2*kp+0) * HDIM + n0 + wn];
        pw[q*2+1] = W[(size_t)(2*kp+1) * HDIM + n0 + wn];
    }
    int buf = 0;
    *(float4*)&sA[0][ar*SA + ah] = pa0;
    *(float4*)&sA[0][ar*SA + ah + 4] = pa1;
    #pragma unroll
    for (int q = 0; q < 4; q++) {
        int kp = wk0 + q * 2;
        sB[0][kp*256 + 2*wn]     = pw[q*2+0];
        sB[0][kp*256 + 2*wn + 1] = pw[q*2+1];
    }
    __syncthreads();

    for (int kt = 0; kt < HDIM / 16; kt++) {
        if (kt < HDIM/16 - 1) {
            const float* An = Ap + (kt + 1) * 16;
            pa0 = *(const float4*)An;
            pa1 = *(const float4*)(An + 4);
            #pragma unroll
            for (int q = 0; q < 4; q++) {
                int kp = wk0 + q * 2;
                int k = (kt + 1) * 16 + 2 * kp;
                pw[q*2+0] = W[(size_t)k * HDIM + n0 + wn];
                pw[q*2+1] = W[(size_t)(k+1) * HDIM + n0 + wn];
            }
        }
        const float* cA = sA[buf];
        const float* cB = sB[buf];
        #pragma unroll
        for (int kq = 0; kq < 4; kq++) {
            ull a0[8], a1[8], w0[8], w1[8];
            #pragma unroll
            for (int i = 0; i < 8; i++) {
                ulonglong2 v = *(const ulonglong2*)&cA[(ty + 16*i) * SA + kq*4];
                a0[i] = v.x; a1[i] = v.y;
            }
            #pragma unroll
            for (int j = 0; j < 8; j++) {
                w0[j] = *(const ull*)&cB[(kq*2+0)*256 + 2*(tx + 16*j)];
                w1[j] = *(const ull*)&cB[(kq*2+1)*256 + 2*(tx + 16*j)];
            }
            #pragma unroll
            for (int i = 0; i < 8; i++)
                #pragma unroll
                for (int j = 0; j < 8; j++) {
                    FFMA2(acc[i][j], a0[i], w0[j]);
                    FFMA2(acc[i][j], a1[i], w1[j]);
                }
        }
        if (kt < HDIM/16 - 1) {
            int nb = buf ^ 1;
            *(float4*)&sA[nb][ar*SA + ah] = pa0;
            *(float4*)&sA[nb][ar*SA + ah + 4] = pa1;
            #pragma unroll
            for (int q = 0; q < 4; q++) {
                int kp = wk0 + q * 2;
                sB[nb][kp*256 + 2*wn]     = pw[q*2+0];
                sB[nb][kp*256 + 2*wn + 1] = pw[q*2+1];
            }
        }
        __syncthreads();
        buf ^= 1;
    }
    #pragma unroll
    for (int j = 0; j < 8; j++) {
        float bb = bias[n0 + tx + 16*j];
        #pragma unroll
        for (int i = 0; i < 8; i++)
            C[(size_t)(m0 + ty + 16*i) * HDIM + n0 + tx + 16*j] = psum(acc[i][j]) + bb;
    }
}

// ---------------------------------------------------------------------------
// Phase 2: persistent scan = R1 structure (128 CTAs, 256 thr, 2x2 tile,
// 128-k double-buffered chunks, R1 barrier) with k-pair FFMA2.
// Split-parity rows: word = idx66 + (pos&1)*32 + (pos>>1)*2 + k_parity,
// giving 1-wavefront LDS.64 for a (broadcast) and w (banks 0,2,..30).
// sW resident (512 kp x 66 = 135KB, loaded once). Staging via STS.64.
// ---------------------------------------------------------------------------
#define STH 66
#define SWW (512 * STH)
#define SCAN_SMEM ((SWW + 2 * 64 * STH) * 4)

__global__ void __launch_bounds__(256, 1) scan_kernel(
    const float* __restrict__ h0, const float* __restrict__ Wh,
    float* __restrict__ out)
{
    extern __shared__ float sm[];
    float* sW = sm;            // [512 kp][66]
    float* sh = sm + SWW;      // [2][64 kp][66]

    const int tid = threadIdx.x;
    const int cg = blockIdx.x, rg = blockIdx.y, c0 = cg * 32;
    const int ty = tid >> 4, tx = tid & 15;   // rows 2ty..+1, cols 2tx..+1

    // one-time: Wh slice in split-parity k-pair layout
    for (int idx = tid; idx < 32 * HDIM; idx += 256) {
        int k = idx >> 5, n = idx & 31;
        sW[(k >> 1) * STH + (n & 1) * 32 + (n >> 1) * 2 + (k & 1)]
            = Wh[(size_t)k * HDIM + c0 + n];
    }
    __syncthreads();

    const int sr = tid >> 3, sx = tid & 7;    // staging: row sr, 16 k per chunk
    const int grow = rg * 32 + sr;
    const int rlo = (sr & 1) * 32 + (sr >> 1) * 2;  // row position in sh word
    int* cnt = &g_cnt[rg * TSTEPS];

    // compute-side fixed offsets
    const int aoff0 = ty * 2;                 // row 2ty   (even)
    const int aoff1 = 32 + ty * 2;            // row 2ty+1 (odd)
    const int woff0 = tx * 2;                 // col 2tx   (even)
    const int woff1 = 32 + tx * 2;            // col 2tx+1 (odd)

    for (int t = 0; t < TSTEPS; t++) {
        const float* hrow = (t == 0)
            ? h0 + (size_t)grow * HDIM
            : out + ((size_t)grow * TSTEPS + (t - 1)) * HDIM;

        ull a00 = 0, a01 = 0, a10 = 0, a11 = 0;

        float4 pf[4];
        #pragma unroll
        for (int q = 0; q < 4; q++)
            pf[q] = *(const float4*)&hrow[sx * 16 + q * 4];

        int buf = 0;
        for (int c = 0; c < 8; c++) {
            // store staged chunk: 4 float4 -> 8 STS.64 in k-pair layout
            {
                float* base = sh + buf * (64 * STH);
                #pragma unroll
                for (int q = 0; q < 4; q++) {
                    int kpl = sx * 8 + q * 2;       // local k-pair of (v.x,v.y)
                    *(float2*)&base[kpl * STH + rlo]
                        = make_float2(pf[q].x, pf[q].y);
                    *(float2*)&base[(kpl + 1) * STH + rlo]
                        = make_float2(pf[q].z, pf[q].w);
                }
            }
            __syncthreads();
            if (c < 7) {
                const float* src = &hrow[(c + 1) * 128 + sx * 16];
                #pragma unroll
                for (int q = 0; q < 4; q++)
                    pf[q] = *(const float4*)&src[q * 4];
            }
            const float* ch = sh + buf * (64 * STH);
            const float* cw = sW + (size_t)c * 64 * STH;
            #pragma unroll 8
            for (int kpl = 0; kpl < 64; kpl++) {
                ull ar0 = *(const ull*)&ch[kpl * STH + aoff0];
                ull ar1 = *(const ull*)&ch[kpl * STH + aoff1];
                ull wc0 = *(const ull*)&cw[kpl * STH + woff0];
                ull wc1 = *(const ull*)&cw[kpl * STH + woff1];
                FFMA2(a00, ar0, wc0);
                FFMA2(a01, ar0, wc1);
                FFMA2(a10, ar1, wc0);
                FFMA2(a11, ar1, wc1);
            }
            buf ^= 1;
        }

        // epilogue: h = tanh(acc + xw), in place
        {
            int m = rg * 32 + 2 * ty;
            float* p0 = out + ((size_t)m * TSTEPS + t) * HDIM + c0 + 2 * tx;
            float* p1 = p0 + (size_t)TSTEPS * HDIM;
            float2 xw0 = *(const float2*)p0;
            float2 xw1 = *(const float2*)p1;
            float2 o0, o1;
            o0.x = tanhf(psum(a00) + xw0.x);
            o0.y = tanhf(psum(a01) + xw0.y);
            o1.x = tanhf(psum(a10) + xw1.x);
            o1.y = tanhf(psum(a11) + xw1.y);
            *(float2*)p0 = o0;
            *(float2*)p1 = o1;
        }

        if (t < TSTEPS - 1) {
            __threadfence();
            __syncthreads();
            if (tid == 0) {
                atomicAdd(cnt + t, 1);
                while (((volatile int*)cnt)[t] < 32) { }
                __threadfence();
            }
            __syncthreads();
        }
    }
}

extern "C" void kernel_launch(void* const* d_in, const int* in_sizes, int n_in,
                              void* d_out, int out_size) {
    const float* x  = (const float*)d_in[0];
    const float* h0 = (const float*)d_in[1];
    const float* Wx = (const float*)d_in[2];
    const float* Wh = (const float*)d_in[3];
    const float* b  = (const float*)d_in[4];
    float* out = (float*)d_out;

    {
        dim3 grid(HDIM / 128, 65536 / 128);
        gemm_xw<<<grid, 256>>>(x, Wx, b, out);
    }
    reset_kernel<<<4, 512>>>();
    {
        static int done = 0;
        if (!done) {
            cudaFuncSetAttribute(scan_kernel,
                cudaFuncAttributeMaxDynamicSharedMemorySize, SCAN_SMEM);
            done = 1;
        }
        dim3 grid(32, 4);
        scan_kernel<<<grid, 256, SCAN_SMEM>>>(h0, Wh, out);
    }
}